// round 12
// baseline (speedup 1.0000x reference)
#include <cuda_runtime.h>
#include <cuda_bf16.h>

// T=4096, B=512, n=32, deg=3. Sequential nonlinear RNN over T.
//
// R12 = R10 numerics (PASS 552us, rel_err 1.6369585e-4, FMA-pipe-bound at
// 127 ops x rt2 = 254 cyc/step) re-laid-out over 4 lanes per chain:
//   - 8 chains/warp, 4 lanes each, lane sub owns states k = sub*8 .. sub*8+7
//   - per-lane scalar updates, VERBATIM R10 expression (same contraction)
//   - all 32 v's exchanged via 32 uniform __shfl_sync; EVERY lane then does
//     the full sequential k=0..31 sum and activation redundantly (no
//     divergence, no fs broadcast) -- every scalar op and its order is
//     bit-identical to R10. Checksum: rel_err must be exactly 0.0001636959.
// R11 lesson: f32x2 is FMA-pipe throughput-neutral (rt~4) => scalar ops.

static constexpr int BATCH = 512;
static constexpr int SPL   = 8;    // states per lane
static constexpr int PF    = 8;    // ring depth == unroll factor

// Lean double-float tanh for x in (0, 9.2]. (verbatim from R10)
__device__ __forceinline__ float tanh_df_lean(float x) {
    const float t  = 2.0f * x;
    const float kf = rintf(t * 1.4426950408889634f);
    const int   ki = (int)kf;

    const float L_h = 0.693147182464599609375f;
    const float L_l = -1.9046542996577634e-9f;
    const float ph = kf * L_h;
    const float pe = fmaf(kf, L_h, -ph);
    const float d  = t - ph;
    const float rh = d - pe;
    const float bb = rh - d;
    const float er = (d - (rh - bb)) + (-pe - bb);
    const float rl = er - kf * L_l;

    const float r2h = rh * rh;
    float r2l = fmaf(rh, rh, -r2h);
    r2l = fmaf(2.0f * rh, rl, r2l);

    float C = fmaf(rh, 2.4801587302e-5f, 1.9841269841e-4f);
    C = fmaf(rh, C, 1.3888888889e-3f);
    C = fmaf(rh, C, 8.3333333333e-3f);
    C = fmaf(rh, C, 4.1666666667e-2f);
    C = fmaf(rh, C, 1.6666666667e-1f);
    const float cub = (r2h * rh) * C;

    const float q  = 0.5f * r2h;
    float mh = rh + q;
    float ml = (rh - mh) + q;
    ml = ml + (cub + (rl + 0.5f * r2l));
    { const float s = mh + ml; ml = ml - (s - mh); mh = s; }

    const float pk = __int_as_float((ki + 127) << 23);
    const float ah = pk * mh;
    const float al = fmaf(pk, ml, fmaf(pk, mh, -ah));

    const float n1 = pk - 1.0f;
    const float nd = n1 - pk;
    const float ne = (pk - (n1 - nd)) + (-1.0f - nd);
    const float nh = n1 + ah;
    const float tb1 = nh - n1;
    const float nl = ((n1 - (nh - tb1)) + (ah - tb1)) + ne + al;

    const float d1 = pk + 1.0f;
    const float dd = d1 - pk;
    const float de = (pk - (d1 - dd)) + (1.0f - dd);
    const float dh = d1 + ah;
    const float tb2 = dh - d1;
    const float dl = ((d1 - (dh - tb2)) + (ah - tb2)) + de + al;

    float rcp;
    asm("rcp.approx.f32 %0, %1;" : "=f"(rcp) : "f"(dh));
    const float q0 = nh * rcp;
    const float e1 = fmaf(-q0, dh, nh);
    const float resid = e1 + fmaf(-q0, dl, nl);
    return fmaf(resid, rcp, q0);
}

__global__ void __launch_bounds__(32, 1)
rnn_firing_rate_r12(const float* __restrict__ currents,   // [T, B]
                    const float* __restrict__ a_vec,      // [n]
                    const float* __restrict__ b_vec,      // [n]
                    const float* __restrict__ ds,         // [n]
                    const float* __restrict__ poly_coeff, // [4]
                    const float* __restrict__ g_b,        // [1]
                    float* __restrict__ out,              // [T, B]
                    int T)
{
    const int lane  = threadIdx.x;
    const int sub   = lane & 3;            // lane within the 4-lane group
    const int gb    = lane & ~3;           // group base lane
    const int batch = blockIdx.x * 8 + (lane >> 2);
    const int kbase = sub * SPL;

    // per-lane slice of constants/state: states k = kbase .. kbase+7
    float av[SPL], bv[SPL], dec[SPL], v[SPL];
    #pragma unroll
    for (int j = 0; j < SPL; ++j) {
        const int k = kbase + j;
        av[j]  = a_vec[k];
        bv[j]  = b_vec[k];
        dec[j] = 1.0f - ds[k];
        v[j]   = 0.0f;
    }
    const float c0 = poly_coeff[0] * poly_coeff[0];
    const float c1 = poly_coeff[1] * poly_coeff[1];
    const float c2 = poly_coeff[2] * poly_coeff[2];
    const float c3 = poly_coeff[3] * poly_coeff[3];
    const float gbv = g_b[0];

    // current prefetch ring (4 lanes of a group load the same address; L1
    // broadcast makes the redundancy free)
    float cbuf[PF];
    #pragma unroll
    for (int i = 0; i < PF; ++i)
        cbuf[i] = (i < T) ? currents[i * BATCH + batch] : 0.0f;

    const float* cptr = currents + (size_t)PF * BATCH + batch;
    float*       optr = out + batch;

    float fs = 0.0f;

    for (int tblk = 0; tblk < T; tblk += PF) {
        #pragma unroll
        for (int u = 0; u < PF; ++u) {
            const int t = tblk + u;
            const float cur = cbuf[u];
            if (t + PF < T) cbuf[u] = cptr[u * BATCH];

            const float h = 1000.0f * fs;   // feedback from PREVIOUS step

            // per-lane update of 8 states: VERBATIM R10 expression, nvcc
            // contraction pattern unchanged.
            #pragma unroll
            for (int j = 0; j < SPL; ++j)
                v[j] = dec[j] * v[j] + cur * av[j] + h * bv[j];

            // exchange: every lane collects ALL 32 v's of its chain.
            // r[g*8+j] = v-state (g*8+j). Uniform shfl, all lanes participate.
            float r[32];
            #pragma unroll
            for (int g = 0; g < 4; ++g) {
                #pragma unroll
                for (int j = 0; j < SPL; ++j)
                    r[g * SPL + j] =
                        __shfl_sync(0xFFFFFFFFu, v[j], gb + g);
            }

            // sequential natural-order sum k=0..31 (pinned rounding order),
            // computed redundantly on every lane => no divergence.
            float s = 0.0f;
            #pragma unroll
            for (int k = 0; k < 32; ++k)
                s += r[k];

            // z = mean(v) - g_b ; poly = c0 + c1 z + c2 z^2 + c3 z^3 (verbatim)
            const float z  = s * (1.0f / 32.0f) - gbv;
            const float z2 = z * z;
            const float z3 = z2 * z;
            const float poly = c0 + c1 * z + c2 * z2 + c3 * z3;

            // fs = relu(100 * tanh(poly)) with exact clip zones (verbatim)
            const bool mid = (poly > 0.0f) && (poly <= 9.2f);
            float fs_mid = 0.0f;
            if (__ballot_sync(0xFFFFFFFFu, mid)) {
                const float th = tanh_df_lean(poly);
                fs_mid = fmaxf(100.0f * th, 0.0f);
            }
            fs = (poly <= 0.0f) ? 0.0f : ((poly > 9.2f) ? 100.0f : fs_mid);

            if (sub == 0) *optr = fs;
            optr += BATCH;
        }
        cptr += PF * BATCH;
    }
}

extern "C" void kernel_launch(void* const* d_in, const int* in_sizes, int n_in,
                              void* d_out, int out_size)
{
    const float* currents   = (const float*)d_in[0];  // [T*B]
    const float* a_vec      = (const float*)d_in[1];  // [32]
    const float* b_vec      = (const float*)d_in[2];  // [32]
    const float* ds         = (const float*)d_in[3];  // [32]
    const float* poly_coeff = (const float*)d_in[4];  // [4]
    const float* g_b        = (const float*)d_in[5];  // [1]
    float* out = (float*)d_out;

    const int T = in_sizes[0] / BATCH;                // 4096

    // 512 chains x 4 lanes = 2048 threads = 64 warps, one warp per block
    rnn_firing_rate_r12<<<BATCH * 4 / 32, 32>>>(currents, a_vec, b_vec, ds,
                                                poly_coeff, g_b, out, T);
}

// round 13
// speedup vs baseline: 1.0704x; 1.0704x over previous
#include <cuda_runtime.h>
#include <cuda_bf16.h>

// T=4096, B=512, n=32, deg=3. Sequential nonlinear RNN over T.
//
// R13: 2 lanes per chain (16 chains/warp, 32 blocks).
//   - even lane owns states 0..15, odd lane owns 16..31
//   - per-lane scalar updates, VERBATIM R10 expression (48 fma instrs/step
//     vs R10's 96)
//   - ONE xor-shuffle exchange (16 SHFLs) gives both lanes all 32 states
//   - both lanes compute the order-pinned sequential sum k=0..31 redundantly,
//     SELs (alu pipe) route own-vs-shuffled into state order
//   - activation / clip zones / lean df tanh / ballot: verbatim
// R12 proved separated update->gather->sequential-sum is bit-identical
// (rel_err exactly 0.0001636959); R12's cost was 32 shuffles — here 16.

static constexpr int BATCH = 512;
static constexpr int SPL   = 16;   // states per lane
static constexpr int PF    = 8;    // ring depth == unroll factor

// Lean double-float tanh for x in (0, 9.2]. (verbatim from R10)
__device__ __forceinline__ float tanh_df_lean(float x) {
    const float t  = 2.0f * x;
    const float kf = rintf(t * 1.4426950408889634f);
    const int   ki = (int)kf;

    const float L_h = 0.693147182464599609375f;
    const float L_l = -1.9046542996577634e-9f;
    const float ph = kf * L_h;
    const float pe = fmaf(kf, L_h, -ph);
    const float d  = t - ph;
    const float rh = d - pe;
    const float bb = rh - d;
    const float er = (d - (rh - bb)) + (-pe - bb);
    const float rl = er - kf * L_l;

    const float r2h = rh * rh;
    float r2l = fmaf(rh, rh, -r2h);
    r2l = fmaf(2.0f * rh, rl, r2l);

    float C = fmaf(rh, 2.4801587302e-5f, 1.9841269841e-4f);
    C = fmaf(rh, C, 1.3888888889e-3f);
    C = fmaf(rh, C, 8.3333333333e-3f);
    C = fmaf(rh, C, 4.1666666667e-2f);
    C = fmaf(rh, C, 1.6666666667e-1f);
    const float cub = (r2h * rh) * C;

    const float q  = 0.5f * r2h;
    float mh = rh + q;
    float ml = (rh - mh) + q;
    ml = ml + (cub + (rl + 0.5f * r2l));
    { const float s = mh + ml; ml = ml - (s - mh); mh = s; }

    const float pk = __int_as_float((ki + 127) << 23);
    const float ah = pk * mh;
    const float al = fmaf(pk, ml, fmaf(pk, mh, -ah));

    const float n1 = pk - 1.0f;
    const float nd = n1 - pk;
    const float ne = (pk - (n1 - nd)) + (-1.0f - nd);
    const float nh = n1 + ah;
    const float tb1 = nh - n1;
    const float nl = ((n1 - (nh - tb1)) + (ah - tb1)) + ne + al;

    const float d1 = pk + 1.0f;
    const float dd = d1 - pk;
    const float de = (pk - (d1 - dd)) + (1.0f - dd);
    const float dh = d1 + ah;
    const float tb2 = dh - d1;
    const float dl = ((d1 - (dh - tb2)) + (ah - tb2)) + de + al;

    float rcp;
    asm("rcp.approx.f32 %0, %1;" : "=f"(rcp) : "f"(dh));
    const float q0 = nh * rcp;
    const float e1 = fmaf(-q0, dh, nh);
    const float resid = e1 + fmaf(-q0, dl, nl);
    return fmaf(resid, rcp, q0);
}

__global__ void __launch_bounds__(32, 1)
rnn_firing_rate_r13(const float* __restrict__ currents,   // [T, B]
                    const float* __restrict__ a_vec,      // [n]
                    const float* __restrict__ b_vec,      // [n]
                    const float* __restrict__ ds,         // [n]
                    const float* __restrict__ poly_coeff, // [4]
                    const float* __restrict__ g_b,        // [1]
                    float* __restrict__ out,              // [T, B]
                    int T)
{
    const int lane  = threadIdx.x;
    const int sub   = lane & 1;             // 0: states 0..15, 1: states 16..31
    const int batch = blockIdx.x * 16 + (lane >> 1);
    const int kbase = sub * SPL;

    // per-lane slice of constants/state
    float av[SPL], bv[SPL], dec[SPL], v[SPL];
    #pragma unroll
    for (int j = 0; j < SPL; ++j) {
        const int k = kbase + j;
        av[j]  = a_vec[k];
        bv[j]  = b_vec[k];
        dec[j] = 1.0f - ds[k];
        v[j]   = 0.0f;
    }
    const float c0 = poly_coeff[0] * poly_coeff[0];
    const float c1 = poly_coeff[1] * poly_coeff[1];
    const float c2 = poly_coeff[2] * poly_coeff[2];
    const float c3 = poly_coeff[3] * poly_coeff[3];
    const float gbv = g_b[0];

    // current prefetch ring (pair lanes load the same address; broadcast)
    float cbuf[PF];
    #pragma unroll
    for (int i = 0; i < PF; ++i)
        cbuf[i] = (i < T) ? currents[i * BATCH + batch] : 0.0f;

    const float* cptr = currents + (size_t)PF * BATCH + batch;
    float*       optr = out + batch;

    float fs = 0.0f;

    for (int tblk = 0; tblk < T; tblk += PF) {
        #pragma unroll
        for (int u = 0; u < PF; ++u) {
            const int t = tblk + u;
            const float cur = cbuf[u];
            if (t + PF < T) cbuf[u] = cptr[u * BATCH];

            const float h = 1000.0f * fs;   // feedback from PREVIOUS step

            // per-lane update of 16 states: VERBATIM R10 expression.
            #pragma unroll
            for (int j = 0; j < SPL; ++j)
                v[j] = dec[j] * v[j] + cur * av[j] + h * bv[j];

            // exchange: one xor-shuffle per slot, both lanes get the other half
            float r[SPL];
            #pragma unroll
            for (int j = 0; j < SPL; ++j)
                r[j] = __shfl_xor_sync(0xFFFFFFFFu, v[j], 1);

            // order-pinned sequential sum k=0..31 on BOTH lanes (redundant).
            // SELs route own-vs-shuffled into global state order.
            float s = 0.0f;
            #pragma unroll
            for (int j = 0; j < SPL; ++j) {     // states 0..15
                const float x = sub ? r[j] : v[j];
                s += x;
            }
            #pragma unroll
            for (int j = 0; j < SPL; ++j) {     // states 16..31
                const float x = sub ? v[j] : r[j];
                s += x;
            }

            // z = mean(v) - g_b ; poly = c0 + c1 z + c2 z^2 + c3 z^3 (verbatim)
            const float z  = s * (1.0f / 32.0f) - gbv;
            const float z2 = z * z;
            const float z3 = z2 * z;
            const float poly = c0 + c1 * z + c2 * z2 + c3 * z3;

            // fs = relu(100 * tanh(poly)) with exact clip zones (verbatim)
            const bool mid = (poly > 0.0f) && (poly <= 9.2f);
            float fs_mid = 0.0f;
            if (__ballot_sync(0xFFFFFFFFu, mid)) {
                const float th = tanh_df_lean(poly);
                fs_mid = fmaxf(100.0f * th, 0.0f);
            }
            fs = (poly <= 0.0f) ? 0.0f : ((poly > 9.2f) ? 100.0f : fs_mid);

            if (sub == 0) *optr = fs;
            optr += BATCH;
        }
        cptr += PF * BATCH;
    }
}

extern "C" void kernel_launch(void* const* d_in, const int* in_sizes, int n_in,
                              void* d_out, int out_size)
{
    const float* currents   = (const float*)d_in[0];  // [T*B]
    const float* a_vec      = (const float*)d_in[1];  // [32]
    const float* b_vec      = (const float*)d_in[2];  // [32]
    const float* ds         = (const float*)d_in[3];  // [32]
    const float* poly_coeff = (const float*)d_in[4];  // [4]
    const float* g_b        = (const float*)d_in[5];  // [1]
    float* out = (float*)d_out;

    const int T = in_sizes[0] / BATCH;                // 4096

    // 512 chains x 2 lanes = 1024 threads = 32 warps, one warp per block
    rnn_firing_rate_r13<<<BATCH * 2 / 32, 32>>>(currents, a_vec, b_vec, ds,
                                                poly_coeff, g_b, out, T);
}